// round 11
// baseline (speedup 1.0000x reference)
#include <cuda_runtime.h>

// Problem constants (fixed by the dataset)
#define B_TOTAL   131072
#define S_DIM     17
#define A_DIM     7
#define DPHI      128
#define DPSI      8

#define NPART     32                  // partial-C blocks
#define I_PER     (DPHI / NPART)      // 4 i-values per block
#define CPS       136                 // padded [17][8] floats per partial
#define CPS4      34                  // ... as float4

#define TILE      256                 // samples per k_main block
#define NBLK_MAIN (B_TOTAL / TILE)    // 512 blocks

// Per-block partial C matrices, padded [17][8] (pad col written as 0).
__device__ float g_Cpart[NPART * CPS];

// ---------------------------------------------------------------------------
// Kernel 1: block p computes partial C over i in [p*I_PER,(p+1)*I_PER).
// Restructured:  T[j,a] = sum_z M[j,z] * Wpsi[z,a]   (896 short chains)
//                C[s,a] = sum_j Wphi[j,s] * T[j,a]   (64-j, 2 accumulators)
// kills the 17x-redundant dependent inner z-loop of the old version.
// Implicit PDL completion trigger covers the g_Cpart writes.
// ---------------------------------------------------------------------------
__global__ __launch_bounds__(256)
void k_partialC(const float* __restrict__ Wphi,   // [128,17]
                const float* __restrict__ Wpsi,   // [8,7]
                const float* __restrict__ K,      // [128,128,8]
                const float* __restrict__ wlin)   // [1,128]
{
    __shared__ float Msm[DPHI * DPSI];   // 1024 floats, layout j*8+z
    __shared__ float Tsm[DPHI * A_DIM];  // 896 floats, layout j*7+a
    __shared__ float Ctmp[256];

    const int p   = blockIdx.x;
    const int tid = threadIdx.x;         // 256 threads

    // --- M partial: each thread owns one float4 of the 1024 floats ---
    {
        const float4* K4 = reinterpret_cast<const float4*>(K);
        float4 acc = make_float4(0.f, 0.f, 0.f, 0.f);
#pragma unroll
        for (int ii = 0; ii < I_PER; ii++) {
            const int i = p * I_PER + ii;
            const float w = __ldg(&wlin[i]);
            const float4 kv = K4[i * 256 + tid];
            acc.x = fmaf(w, kv.x, acc.x);
            acc.y = fmaf(w, kv.y, acc.y);
            acc.z = fmaf(w, kv.z, acc.z);
            acc.w = fmaf(w, kv.w, acc.w);
        }
        reinterpret_cast<float4*>(Msm)[tid] = acc;
    }
    __syncthreads();

    // --- T[j,a] = sum_z M[j,z] * Wpsi[z,a]; 896 entries, <=4 per thread ---
#pragma unroll
    for (int e = tid; e < DPHI * A_DIM; e += 256) {
        const int j = e / A_DIM;
        const int a = e - j * A_DIM;
        float t0 = 0.f, t1 = 0.f;        // 2 chains of 4
#pragma unroll
        for (int z = 0; z < 4; z++) {
            t0 = fmaf(Msm[j * DPSI + z],     __ldg(&Wpsi[z * A_DIM + a]),       t0);
            t1 = fmaf(Msm[j * DPSI + 4 + z], __ldg(&Wpsi[(4 + z) * A_DIM + a]), t1);
        }
        Tsm[e] = t0 + t1;
    }
    __syncthreads();

    // --- C partial: 2 threads per (s,a), 64 j each, 2 accumulators ---
    float c = 0.f;
    if (tid < 2 * S_DIM * A_DIM) {       // 238 active threads
        const int o    = tid >> 1;
        const int half = tid & 1;
        const int s = o / A_DIM;
        const int a = o - s * A_DIM;

        const int j0 = half * 64;
        float c0 = 0.f, c1 = 0.f;
#pragma unroll 8
        for (int j = j0; j < j0 + 64; j += 2) {
            c0 = fmaf(__ldg(&Wphi[j * S_DIM + s]),       Tsm[j * A_DIM + a],       c0);
            c1 = fmaf(__ldg(&Wphi[(j + 1) * S_DIM + s]), Tsm[(j + 1) * A_DIM + a], c1);
        }
        c = c0 + c1;
    }
    Ctmp[tid] = c;
    __syncthreads();

    // --- store padded [17][8]; pad column = 0 ---
    if (tid < CPS) {
        const int row = tid >> 3;
        const int col = tid & 7;
        float v = 0.f;
        if (col < A_DIM) {
            const int o = row * A_DIM + col;
            v = Ctmp[2 * o] + Ctmp[2 * o + 1];
        }
        g_Cpart[p * CPS + tid] = v;
    }
}

// ---------------------------------------------------------------------------
// Kernel 2 (PDL secondary, R2-best shape): out[b] = state[b]^T C action[b]
// 512 blocks x 256 thr, TILE=256, direct float4 smem staging, gridDepSync
// after staging, 34-thread C reduce, single barrier.
// ---------------------------------------------------------------------------
__global__ __launch_bounds__(256)
void k_main(const float* __restrict__ state,   // [B,17]
            const float* __restrict__ action,  // [B,7]
            float* __restrict__ out)           // [B]
{
    __shared__ __align__(16) float Ss[TILE * S_DIM];   // 4352 floats
    __shared__ __align__(16) float As[TILE * A_DIM];   // 1792 floats
    __shared__ __align__(16) float Csm[CPS];           // padded [17][8]

    const int tid = threadIdx.x;
    const int bx  = blockIdx.x;

    // --- stage state tile: 1088 float4 = 4 full rounds + 64 ---
    {
        const float4* S4 = reinterpret_cast<const float4*>(state) + (size_t)bx * 1088;
        float4* D = reinterpret_cast<float4*>(Ss);
#pragma unroll
        for (int k = 0; k < 4; k++) D[tid + k * 256] = S4[tid + k * 256];
        if (tid < 64) D[tid + 1024] = S4[tid + 1024];
    }
    // --- stage action tile: 448 float4 = 1 full round + 192 ---
    {
        const float4* A4 = reinterpret_cast<const float4*>(action) + (size_t)bx * 448;
        float4* D = reinterpret_cast<float4*>(As);
        D[tid] = A4[tid];
        if (tid < 192) D[tid + 256] = A4[tid + 256];
    }

    // --- wait for k1 (overlaps the staging above) ---
    cudaGridDependencySynchronize();

    // --- partial-C reduce: 34 threads x 32 float4 L2 loads, fixed order ---
    if (tid < CPS4) {
        const float4* P4 = reinterpret_cast<const float4*>(g_Cpart);
        float4 cred = make_float4(0.f, 0.f, 0.f, 0.f);
#pragma unroll 8
        for (int pp = 0; pp < NPART; pp++) {
            const float4 x = P4[pp * CPS4 + tid];
            cred.x += x.x; cred.y += x.y; cred.z += x.z; cred.w += x.w;
        }
        reinterpret_cast<float4*>(Csm)[tid] = cred;
    }

    __syncthreads();   // single barrier

    // --- per-sample bilinear form ---
    const float* av = As + tid * A_DIM;    // lane stride 7: conflict-free
    const float v0 = av[0], v1 = av[1], v2 = av[2], v3 = av[3];
    const float v4 = av[4], v5 = av[5], v6 = av[6];

    const float4* C4 = reinterpret_cast<const float4*>(Csm);
    const float*  st = Ss + tid * S_DIM;   // lane stride 17: conflict-free

    float r = 0.f;
#pragma unroll
    for (int s = 0; s < S_DIM; s++) {
        const float4 c0 = C4[2 * s];       // broadcast LDS.128
        const float4 c1 = C4[2 * s + 1];   // C[s][4..6], pad
        float t;
        t = c0.x * v0;
        t = fmaf(c0.y, v1, t);
        t = fmaf(c0.z, v2, t);
        t = fmaf(c0.w, v3, t);
        t = fmaf(c1.x, v4, t);
        t = fmaf(c1.y, v5, t);
        t = fmaf(c1.z, v6, t);
        r = fmaf(st[s], t, r);
    }

    out[bx * TILE + tid] = r;
}

// ---------------------------------------------------------------------------
extern "C" void kernel_launch(void* const* d_in, const int* in_sizes, int n_in,
                              void* d_out, int out_size)
{
    const float* state  = (const float*)d_in[0];
    const float* action = (const float*)d_in[1];
    const float* Wphi   = (const float*)d_in[2];
    const float* Wpsi   = (const float*)d_in[3];
    const float* K      = (const float*)d_in[4];
    const float* wlin   = (const float*)d_in[5];
    float* out = (float*)d_out;

    k_partialC<<<NPART, 256>>>(Wphi, Wpsi, K, wlin);

    // PDL secondary launch: overlap with k_partialC.
    cudaLaunchConfig_t cfg = {};
    cfg.gridDim  = dim3(NBLK_MAIN, 1, 1);
    cfg.blockDim = dim3(256, 1, 1);
    cfg.dynamicSmemBytes = 0;
    cfg.stream = 0;
    cudaLaunchAttribute attr[1];
    attr[0].id = cudaLaunchAttributeProgrammaticStreamSerialization;
    attr[0].val.programmaticStreamSerializationAllowed = 1;
    cfg.attrs    = attr;
    cfg.numAttrs = 1;
    cudaLaunchKernelEx(&cfg, k_main, state, action, out);
}